// round 9
// baseline (speedup 1.0000x reference)
#include <cuda_runtime.h>
#include <cuda_fp16.h>
#include <cstdint>

// Problem constants
#define BATCH 2048
#define TT    609
#define NIN   5
#define HH    8
#define D_LSTM (TT * HH)     // 4872
#define N1    4096
#define N2    1024
#define N3    609            // == TT

// Scratch (no cudaMalloc allowed) ---------------------------------------------
__device__ __half g_lstm_h[BATCH * D_LSTM];    // [2048, 4872] fp16
__device__ __half g_a1h[BATCH * N1];           // [2048, 4096] fp16
__device__ __half g_a2h[BATCH * N2];           // [2048, 1024] fp16
__device__ __half g_w1h[N1 * D_LSTM];          // fp16 W1
__device__ __half g_w2h[N2 * N1];              // fp16 W2
__device__ __half g_w3h[N3 * N2];              // fp16 W3

// ---------------------------------------------------------------------------
// weight fp32 -> fp16 conversion (once per launch)
// ---------------------------------------------------------------------------
__global__ void cvt_w_half(const float4* __restrict__ src, __half2* __restrict__ dst, int n4)
{
    int i = blockIdx.x * blockDim.x + threadIdx.x;
    if (i < n4) {
        float4 v = src[i];
        dst[2 * i + 0] = __floats2half2_rn(v.x, v.y);
        dst[2 * i + 1] = __floats2half2_rn(v.z, v.w);
    }
}

// ---------------------------------------------------------------------------
// LSTM cell step, 2 batch elements (ILP x2), 16 lanes per element.
//   half==0 thread: gate rows j (i) and 16+j (g)
//   half==1 thread: gate rows 8+j (f) and 24+j (o)
// Identical math/order to R8 (bit-identical numerics).
// ---------------------------------------------------------------------------

__device__ __forceinline__ float sigmoidf_fast(float v) {
    float e = __expf(-v);
    return __fdividef(1.0f, 1.0f + e);
}

template <int NI>
__device__ __forceinline__ void cell_step2(
    const float* wA, const float* wB,
    const float* uA, const float* uB,
    float bA, float bB,
    const float* in0, const float* in1,
    float* h0, float* h1,
    float& c0, float& c1, int half,
    float& hv0, float& hv1)
{
    float gA0a = bA, gA0b = 0.f, gB0a = bB, gB0b = 0.f;
    float gA1a = bA, gA1b = 0.f, gB1a = bB, gB1b = 0.f;
#pragma unroll
    for (int i = 0; i < NI; i++) {
        if (i & 1) {
            gA0b = fmaf(wA[i], in0[i], gA0b);
            gA1b = fmaf(wA[i], in1[i], gA1b);
            gB0b = fmaf(wB[i], in0[i], gB0b);
            gB1b = fmaf(wB[i], in1[i], gB1b);
        } else {
            gA0a = fmaf(wA[i], in0[i], gA0a);
            gA1a = fmaf(wA[i], in1[i], gA1a);
            gB0a = fmaf(wB[i], in0[i], gB0a);
            gB1a = fmaf(wB[i], in1[i], gB1a);
        }
    }
#pragma unroll
    for (int k = 0; k < HH; k++) {
        if (k & 1) {
            gA0b = fmaf(uA[k], h0[k], gA0b);
            gA1b = fmaf(uA[k], h1[k], gA1b);
            gB0b = fmaf(uB[k], h0[k], gB0b);
            gB1b = fmaf(uB[k], h1[k], gB1b);
        } else {
            gA0a = fmaf(uA[k], h0[k], gA0a);
            gA1a = fmaf(uA[k], h1[k], gA1a);
            gB0a = fmaf(uB[k], h0[k], gB0a);
            gB1a = fmaf(uB[k], h1[k], gB1a);
        }
    }
    float gA0 = gA0a + gA0b, gB0 = gB0a + gB0b;
    float gA1 = gA1a + gA1b, gB1 = gB1a + gB1b;

    float va0 = sigmoidf_fast(gA0);
    float va1 = sigmoidf_fast(gA1);
    float e0 = __expf(half ? -gB0 : (-2.0f * gB0));
    float e1 = __expf(half ? -gB1 : (-2.0f * gB1));
    float r0 = __fdividef(1.0f, 1.0f + e0);
    float r1 = __fdividef(1.0f, 1.0f + e1);
    float vb0 = half ? r0 : fmaf(2.0f, r0, -1.0f);
    float vb1 = half ? r1 : fmaf(2.0f, r1, -1.0f);

    float pa0 = __shfl_xor_sync(0xffffffffu, va0, 8);
    float pa1 = __shfl_xor_sync(0xffffffffu, va1, 8);
    float pb0 = __shfl_xor_sync(0xffffffffu, vb0, 8);
    float pb1 = __shfl_xor_sync(0xffffffffu, vb1, 8);

    c0 = fmaf(pa0, c0, va0 * vb0);
    c1 = fmaf(pa1, c1, va1 * vb1);
    float th0 = fmaf(2.0f, __fdividef(1.0f, 1.0f + __expf(-2.0f * c0)), -1.0f);
    float th1 = fmaf(2.0f, __fdividef(1.0f, 1.0f + __expf(-2.0f * c1)), -1.0f);
    hv0 = pb0 * th0;
    hv1 = pb1 * th1;

#pragma unroll
    for (int k = 0; k < HH; k++) {
        h0[k] = __shfl_sync(0xffffffffu, hv0, k, 16);
        h1[k] = __shfl_sync(0xffffffffu, hv1, k, 16);
    }
}

// ---------------------------------------------------------------------------
// Warp-specialized 3-layer LSTM pipeline: block = 96 threads = 3 warps.
// Warp w computes layer w+1. Block owns 4 batch elements (2 groups x 2 ILP).
// h handoff via 2-slot smem ring, one __syncthreads per timestep.
//   iter i: warp0 -> L1 @ t=i, warp1 -> L2 @ t=i-1, warp2 -> L3 @ t=i-2
// ---------------------------------------------------------------------------
__global__ __launch_bounds__(96)
void lstm3_pipe(
    const float* __restrict__ x,
    const float* __restrict__ Wih1, const float* __restrict__ Whh1,
    const float* __restrict__ bih1, const float* __restrict__ bhh1,
    const float* __restrict__ Wih2, const float* __restrict__ Whh2,
    const float* __restrict__ bih2, const float* __restrict__ bhh2,
    const float* __restrict__ Wih3, const float* __restrict__ Whh3,
    const float* __restrict__ bih3, const float* __restrict__ bhh3,
    __half* __restrict__ out)
{
    const int tid  = threadIdx.x;
    const int warp = tid >> 5;            // 0,1,2 -> layer
    const int lane = tid & 31;
    const int grp  = lane >> 4;           // 0,1
    const int sub  = lane & 15;
    const int j    = sub & 7;
    const int half = sub >> 3;

    const int e0   = blockIdx.x * 4 + grp * 2;   // this group's elems: e0, e0+1
    const int eg   = grp * 2;                    // smem elem index base

    const int rowA = half * 8 + j;
    const int rowB = 16 + half * 8 + j;

    __shared__ float h1buf[2][4][HH];
    __shared__ float h2buf[2][4][HH];

    // ---- per-warp weight load ----
    float wiA[8], wiB[8], uhA[8], uhB[8];
    float bA = 0.f, bB = 0.f;
    if (warp == 0) {
#pragma unroll
        for (int i = 0; i < 8; i++) { wiA[i] = 0.f; wiB[i] = 0.f; }
#pragma unroll
        for (int i = 0; i < NIN; i++) {
            wiA[i] = Wih1[rowA * NIN + i];
            wiB[i] = Wih1[rowB * NIN + i];
        }
#pragma unroll
        for (int k = 0; k < HH; k++) {
            uhA[k] = Whh1[rowA * HH + k];
            uhB[k] = Whh1[rowB * HH + k];
        }
        bA = bih1[rowA] + bhh1[rowA];
        bB = bih1[rowB] + bhh1[rowB];
    } else if (warp == 1) {
#pragma unroll
        for (int k = 0; k < HH; k++) {
            wiA[k] = Wih2[rowA * HH + k];
            wiB[k] = Wih2[rowB * HH + k];
            uhA[k] = Whh2[rowA * HH + k];
            uhB[k] = Whh2[rowB * HH + k];
        }
        bA = bih2[rowA] + bhh2[rowA];
        bB = bih2[rowB] + bhh2[rowB];
    } else {
#pragma unroll
        for (int k = 0; k < HH; k++) {
            wiA[k] = Wih3[rowA * HH + k];
            wiB[k] = Wih3[rowB * HH + k];
            uhA[k] = Whh3[rowA * HH + k];
            uhB[k] = Whh3[rowB * HH + k];
        }
        bA = bih3[rowA] + bhh3[rowA];
        bB = bih3[rowB] + bhh3[rowB];
    }

    // ---- own recurrent state (this warp's layer) ----
    float h0[HH], h1[HH];
#pragma unroll
    for (int k = 0; k < HH; k++) { h0[k] = 0.f; h1[k] = 0.f; }
    float c0 = 0.f, c1 = 0.f;
    float hv0, hv1;

    // warp0 input prefetch
    const float* xr0 = x + (size_t)e0 * TT * NIN;
    const float* xr1 = xr0 + (size_t)TT * NIN;
    float xn0[NIN], xn1[NIN];
    if (warp == 0) {
#pragma unroll
        for (int i = 0; i < NIN; i++) { xn0[i] = xr0[i]; xn1[i] = xr1[i]; }
    }

    __half* op0 = out + (size_t)e0 * D_LSTM;
    __half* op1 = op0 + D_LSTM;

    __syncthreads();   // smem ready (nothing written yet; uniform start)

    for (int i = 0; i < TT + 2; i++) {
        if (warp == 0) {
            if (i < TT) {
                float xc0[NIN], xc1[NIN];
#pragma unroll
                for (int q = 0; q < NIN; q++) { xc0[q] = xn0[q]; xc1[q] = xn1[q]; }
                const int tn = (i + 1 < TT) ? (i + 1) : (TT - 1);
#pragma unroll
                for (int q = 0; q < NIN; q++) {
                    xn0[q] = xr0[tn * NIN + q];
                    xn1[q] = xr1[tn * NIN + q];
                }
                cell_step2<NIN>(wiA, wiB, uhA, uhB, bA, bB,
                                xc0, xc1, h0, h1, c0, c1, half, hv0, hv1);
                if (half == 0) {
                    h1buf[i & 1][eg    ][j] = hv0;
                    h1buf[i & 1][eg + 1][j] = hv1;
                }
            }
        } else if (warp == 1) {
            if (i >= 1 && i < TT + 1) {
                const int rs = (i - 1) & 1;
                float in0[HH], in1[HH];
#pragma unroll
                for (int k = 0; k < HH; k++) {
                    in0[k] = h1buf[rs][eg    ][k];
                    in1[k] = h1buf[rs][eg + 1][k];
                }
                cell_step2<HH>(wiA, wiB, uhA, uhB, bA, bB,
                               in0, in1, h0, h1, c0, c1, half, hv0, hv1);
                if (half == 0) {
                    h2buf[i & 1][eg    ][j] = hv0;
                    h2buf[i & 1][eg + 1][j] = hv1;
                }
            }
        } else {
            if (i >= 2) {
                const int rs = (i - 1) & 1;
                const int t  = i - 2;
                float in0[HH], in1[HH];
#pragma unroll
                for (int k = 0; k < HH; k++) {
                    in0[k] = h2buf[rs][eg    ][k];
                    in1[k] = h2buf[rs][eg + 1][k];
                }
                cell_step2<HH>(wiA, wiB, uhA, uhB, bA, bB,
                               in0, in1, h0, h1, c0, c1, half, hv0, hv1);
                if (half == 0) {
                    op0[t * HH + j] = __float2half_rn(hv0);
                    op1[t * HH + j] = __float2half_rn(hv1);
                }
            }
        }
        __syncthreads();
    }
}

// ---------------------------------------------------------------------------
// fp16 tensor-core GEMM (fp32 accumulate): C = A[M,K] @ W[N,K]^T + bias.
// cp.async double-buffered, 2x2 warps, fragment double-buffering. (unchanged)
// ---------------------------------------------------------------------------

__device__ __forceinline__ void cp_async16(uint32_t dst, const void* src, int src_bytes) {
    asm volatile("cp.async.cg.shared.global [%0], [%1], 16, %2;\n"
                 :: "r"(dst), "l"(src), "r"(src_bytes));
}
__device__ __forceinline__ void cp_commit() {
    asm volatile("cp.async.commit_group;\n" ::: "memory");
}
template <int N>
__device__ __forceinline__ void cp_wait() {
    asm volatile("cp.async.wait_group %0;\n" :: "n"(N) : "memory");
}

__device__ __forceinline__ void mma_f16(float (&c)[4], const uint32_t (&a)[4],
                                        const uint32_t (&b)[2]) {
    asm volatile(
        "mma.sync.aligned.m16n8k16.row.col.f32.f16.f16.f32 "
        "{%0,%1,%2,%3}, {%4,%5,%6,%7}, {%8,%9}, {%0,%1,%2,%3};"
        : "+f"(c[0]), "+f"(c[1]), "+f"(c[2]), "+f"(c[3])
        : "r"(a[0]), "r"(a[1]), "r"(a[2]), "r"(a[3]), "r"(b[0]), "r"(b[1]));
}

template <int BM, int BN, bool RELU, bool OUT_HALF>
__global__ __launch_bounds__(128, 2)
void gemm_f16(const __half* __restrict__ A, const __half* __restrict__ W,
              const float* __restrict__ bias, void* __restrict__ Cv,
              int M, int N, int K)
{
    constexpr int BK = 64;
    constexpr int THREADS = 128;
    constexpr int WARPS_M = 2, WARPS_N = 2;
    constexpr int WM = BM / WARPS_M;
    constexpr int WN = BN / WARPS_N;
    constexpr int MT = WM / 16;
    constexpr int NT = WN / 8;
    constexpr int LDW = BK / 2 + 4;

    extern __shared__ uint32_t sm[];
    uint32_t* As = sm;
    uint32_t* Bs = sm + 2 * BM * LDW;

    const int tid  = threadIdx.x;
    const int lane = tid & 31;
    const int warp = tid >> 5;
    const int wm   = warp / WARPS_N;
    const int wn   = warp % WARPS_N;
    const int g    = lane >> 2;
    const int t    = lane & 3;

    const int m0 = blockIdx.y * BM;
    const int n0 = blockIdx.x * BN;

    const uint32_t as_smem = (uint32_t)__cvta_generic_to_shared(As);
    const uint32_t bs_smem = (uint32_t)__cvta_generic_to_shared(Bs);

    float acc[MT][NT][4];
#pragma unroll
    for (int i = 0; i < MT; i++)
#pragma unroll
        for (int j = 0; j < NT; j++)
#pragma unroll
            for (int q = 0; q < 4; q++) acc[i][j][q] = 0.f;

    constexpr int KQ = BK / 8;
    constexpr int A_ITERS = BM * KQ / THREADS;
    constexpr int B_ITERS = BN * KQ / THREADS;

    auto load_tiles = [&](int k0, int stage) {
        const uint32_t a_base = as_smem + (uint32_t)stage * BM * LDW * 4;
        const uint32_t b_base = bs_smem + (uint32_t)stage * BN * LDW * 4;
#pragma unroll
        for (int r = 0; r < A_ITERS; r++) {
            const int idx = tid + r * THREADS;
            const int row = idx / KQ;
            const int kq  = idx % KQ;
            const int kg  = k0 + kq * 8;
            const bool ok = kg < K;
            const __half* src = ok ? &A[(size_t)(m0 + row) * K + kg] : A;
            cp_async16(a_base + (row * LDW + kq * 4) * 4, src, ok ? 16 : 0);
        }
#pragma unroll
        for (int r = 0; r < B_ITERS; r++) {
            const int idx = tid + r * THREADS;
            const int row = idx / KQ;
            const int kq  = idx % KQ;
            const int kg  = k0 + kq * 8;
            const bool ok = (n0 + row) < N && kg < K;
            const __half* src = ok ? &W[(size_t)(n0 + row) * K + kg] : W;
            cp_async16(b_base + (row * LDW + kq * 4) * 4, src, ok ? 16 : 0);
        }
        cp_commit();
    };

    const int nk = (K + BK - 1) / BK;

    load_tiles(0, 0);

    uint32_t af[2][MT][4], bf[2][NT][2];

    for (int it = 0; it < nk; it++) {
        const int cur = it & 1;
        if (it + 1 < nk) {
            load_tiles((it + 1) * BK, (it + 1) & 1);
            cp_wait<1>();
        } else {
            cp_wait<0>();
        }
        __syncthreads();

        const uint32_t* Ac = As + cur * BM * LDW;
        const uint32_t* Bc = Bs + cur * BN * LDW;

        auto ldfrag = [&](int ks, int buf) {
            const int wb = ks * 8;
#pragma unroll
            for (int mt = 0; mt < MT; mt++) {
                const int r = wm * WM + mt * 16 + g;
                af[buf][mt][0] = Ac[(r    ) * LDW + wb + t    ];
                af[buf][mt][1] = Ac[(r + 8) * LDW + wb + t    ];
                af[buf][mt][2] = Ac[(r    ) * LDW + wb + t + 4];
                af[buf][mt][3] = Ac[(r + 8) * LDW + wb + t + 4];
            }
#pragma unroll
            for (int nt = 0; nt < NT; nt++) {
                const int cc = wn * WN + nt * 8 + g;
                bf[buf][nt][0] = Bc[cc * LDW + wb + t    ];
                bf[buf][nt][1] = Bc[cc * LDW + wb + t + 4];
            }
        };

        ldfrag(0, 0);
#pragma unroll
        for (int ks = 0; ks < 4; ks++) {
            const int cb = ks & 1;
            if (ks + 1 < 4)
                ldfrag(ks + 1, cb ^ 1);
#pragma unroll
            for (int mt = 0; mt < MT; mt++)
#pragma unroll
                for (int nt = 0; nt < NT; nt++)
                    mma_f16(acc[mt][nt], af[cb][mt], bf[cb][nt]);
        }
        __syncthreads();
    }

#pragma unroll
    for (int mt = 0; mt < MT; mt++) {
        const int r0 = m0 + wm * WM + mt * 16 + g;
        const int r1 = r0 + 8;
#pragma unroll
        for (int nt = 0; nt < NT; nt++) {
            const int cbase = n0 + wn * WN + nt * 8 + 2 * t;
            if (OUT_HALF) {
                const float bv0 = bias[cbase], bv1 = bias[cbase + 1];
                float v00 = acc[mt][nt][0] + bv0;
                float v01 = acc[mt][nt][1] + bv1;
                float v10 = acc[mt][nt][2] + bv0;
                float v11 = acc[mt][nt][3] + bv1;
                if (RELU) {
                    v00 = fmaxf(v00, 0.f); v01 = fmaxf(v01, 0.f);
                    v10 = fmaxf(v10, 0.f); v11 = fmaxf(v11, 0.f);
                }
                __half2* C = (__half2*)Cv;
                C[((size_t)r0 * N + cbase) >> 1] = __floats2half2_rn(v00, v01);
                C[((size_t)r1 * N + cbase) >> 1] = __floats2half2_rn(v10, v11);
            } else {
                float* C = (float*)Cv;
#pragma unroll
                for (int q = 0; q < 2; q++) {
                    const int cn = cbase + q;
                    if (cn < N) {
                        const float bv = bias[cn];
                        float v0 = acc[mt][nt][q] + bv;
                        float v1 = acc[mt][nt][2 + q] + bv;
                        if (RELU) { v0 = fmaxf(v0, 0.f); v1 = fmaxf(v1, 0.f); }
                        C[(size_t)r0 * N + cn] = v0;
                        C[(size_t)r1 * N + cn] = v1;
                    }
                }
            }
        }
    }
}

// ---------------------------------------------------------------------------
extern "C" void kernel_launch(void* const* d_in, const int* in_sizes, int n_in,
                              void* d_out, int out_size)
{
    const float* x    = (const float*)d_in[0];
    const float* Wih1 = (const float*)d_in[1];
    const float* Whh1 = (const float*)d_in[2];
    const float* bih1 = (const float*)d_in[3];
    const float* bhh1 = (const float*)d_in[4];
    const float* Wih2 = (const float*)d_in[5];
    const float* Whh2 = (const float*)d_in[6];
    const float* bih2 = (const float*)d_in[7];
    const float* bhh2 = (const float*)d_in[8];
    const float* Wih3 = (const float*)d_in[9];
    const float* Whh3 = (const float*)d_in[10];
    const float* bih3 = (const float*)d_in[11];
    const float* bhh3 = (const float*)d_in[12];
    const float* W1   = (const float*)d_in[13];
    const float* b1   = (const float*)d_in[14];
    const float* W2   = (const float*)d_in[15];
    const float* b2   = (const float*)d_in[16];
    const float* W3   = (const float*)d_in[17];
    const float* b3   = (const float*)d_in[18];
    float* out = (float*)d_out;

    __half *lstm_h, *a1h, *a2h, *w1h, *w2h, *w3h;
    cudaGetSymbolAddress((void**)&lstm_h, g_lstm_h);
    cudaGetSymbolAddress((void**)&a1h, g_a1h);
    cudaGetSymbolAddress((void**)&a2h, g_a2h);
    cudaGetSymbolAddress((void**)&w1h, g_w1h);
    cudaGetSymbolAddress((void**)&w2h, g_w2h);
    cudaGetSymbolAddress((void**)&w3h, g_w3h);

    constexpr int LDW = 36;
    constexpr int SMEM_128 = (2 * 128 * LDW + 2 * 128 * LDW) * 4;  // 73728
    constexpr int SMEM_64  = (2 * 128 * LDW + 2 * 64 * LDW) * 4;   // 55296

    static bool attr_done = false;
    if (!attr_done) {
        cudaFuncSetAttribute(gemm_f16<128, 128, true, true>,
                             cudaFuncAttributeMaxDynamicSharedMemorySize, SMEM_128);
        cudaFuncSetAttribute(gemm_f16<128, 64, true, true>,
                             cudaFuncAttributeMaxDynamicSharedMemorySize, SMEM_64);
        cudaFuncSetAttribute(gemm_f16<128, 64, false, false>,
                             cudaFuncAttributeMaxDynamicSharedMemorySize, SMEM_64);
        attr_done = true;
    }

    // 0) pre-convert weights to fp16
    {
        const int n4_1 = N1 * D_LSTM / 4;
        const int n4_2 = N2 * N1 / 4;
        const int n4_3 = N3 * N2 / 4;
        cvt_w_half<<<(n4_1 + 255) / 256, 256>>>((const float4*)W1, (__half2*)w1h, n4_1);
        cvt_w_half<<<(n4_2 + 255) / 256, 256>>>((const float4*)W2, (__half2*)w2h, n4_2);
        cvt_w_half<<<(n4_3 + 255) / 256, 256>>>((const float4*)W3, (__half2*)w3h, n4_3);
    }

    // 1) warp-specialized 3-layer LSTM pipeline: 512 blocks x 96 threads
    lstm3_pipe<<<BATCH / 4, 96>>>(x,
        Wih1, Whh1, bih1, bhh1,
        Wih2, Whh2, bih2, bhh2,
        Wih3, Whh3, bih3, bhh3,
        lstm_h);

    // 2) MLP head (fp16 mma, fp32 accumulate)
    {   // [2048,4872] x [4096,4872]^T -> relu -> [2048,4096] fp16
        dim3 grid(N1 / 128, BATCH / 128);
        gemm_f16<128, 128, true, true><<<grid, 128, SMEM_128>>>(
            lstm_h, w1h, b1, a1h, BATCH, N1, D_LSTM);
    }
    {   // [2048,4096] x [1024,4096]^T -> relu -> [2048,1024] fp16
        dim3 grid(N2 / 64, BATCH / 128);
        gemm_f16<128, 64, true, true><<<grid, 128, SMEM_64>>>(
            a1h, w2h, b2, a2h, BATCH, N2, N1);
    }
    {   // [2048,1024] x [609,1024]^T -> [2048,609] fp32
        dim3 grid((N3 + 63) / 64, BATCH / 128);
        gemm_f16<128, 64, false, false><<<grid, 128, SMEM_64>>>(
            a2h, w3h, b3, out, BATCH, N3, N2);
    }
}

// round 10
// speedup vs baseline: 1.0996x; 1.0996x over previous
#include <cuda_runtime.h>
#include <cuda_fp16.h>
#include <cstdint>

// Problem constants
#define BATCH 2048
#define TT    609
#define NIN   5
#define HH    8
#define D_LSTM (TT * HH)     // 4872
#define N1    4096
#define N2    1024
#define N3    609            // == TT

// Scratch (no cudaMalloc allowed) ---------------------------------------------
__device__ __half g_lstm_h[BATCH * D_LSTM];    // [2048, 4872] fp16
__device__ __half g_a1h[BATCH * N1];           // [2048, 4096] fp16
__device__ __half g_a2h[BATCH * N2];           // [2048, 1024] fp16
__device__ __half g_w1h[N1 * D_LSTM];          // fp16 W1
__device__ __half g_w2h[N2 * N1];              // fp16 W2
__device__ __half g_w3h[N3 * N2];              // fp16 W3

// ---------------------------------------------------------------------------
// weight fp32 -> fp16 conversion (once per launch)
// ---------------------------------------------------------------------------
__global__ void cvt_w_half(const float4* __restrict__ src, __half2* __restrict__ dst, int n4)
{
    int i = blockIdx.x * blockDim.x + threadIdx.x;
    if (i < n4) {
        float4 v = src[i];
        dst[2 * i + 0] = __floats2half2_rn(v.x, v.y);
        dst[2 * i + 1] = __floats2half2_rn(v.z, v.w);
    }
}

// ---------------------------------------------------------------------------
// Fused 3-layer LSTM with LAYER SKEW (R8 structure) + HW tanh activations.
//   sigmoid(x) = 0.5*tanh(0.5x)+0.5  (1 MUFU)  |  tanh: 1 MUFU
// Halves MUFU pipe pressure and shortens the serial activation chain.
// ---------------------------------------------------------------------------

__device__ __forceinline__ float tanh_hw(float x) {
    float y;
    asm("tanh.approx.f32 %0, %1;" : "=f"(y) : "f"(x));
    return y;
}

template <int NI>
__device__ __forceinline__ void cell_step2(
    const float (&wA)[NI], const float (&wB)[NI],
    const float (&uA)[HH], const float (&uB)[HH],
    float bA, float bB,
    const float (&in0)[NI], const float (&in1)[NI],
    float (&h0)[HH], float (&h1)[HH],
    float& c0, float& c1, int half,
    float& hv0, float& hv1)
{
    float gA0a = bA, gA0b = 0.f, gB0a = bB, gB0b = 0.f;
    float gA1a = bA, gA1b = 0.f, gB1a = bB, gB1b = 0.f;
#pragma unroll
    for (int i = 0; i < NI; i++) {
        if (i & 1) {
            gA0b = fmaf(wA[i], in0[i], gA0b);
            gA1b = fmaf(wA[i], in1[i], gA1b);
            gB0b = fmaf(wB[i], in0[i], gB0b);
            gB1b = fmaf(wB[i], in1[i], gB1b);
        } else {
            gA0a = fmaf(wA[i], in0[i], gA0a);
            gA1a = fmaf(wA[i], in1[i], gA1a);
            gB0a = fmaf(wB[i], in0[i], gB0a);
            gB1a = fmaf(wB[i], in1[i], gB1a);
        }
    }
#pragma unroll
    for (int k = 0; k < HH; k++) {
        if (k & 1) {
            gA0b = fmaf(uA[k], h0[k], gA0b);
            gA1b = fmaf(uA[k], h1[k], gA1b);
            gB0b = fmaf(uB[k], h0[k], gB0b);
            gB1b = fmaf(uB[k], h1[k], gB1b);
        } else {
            gA0a = fmaf(uA[k], h0[k], gA0a);
            gA1a = fmaf(uA[k], h1[k], gA1a);
            gB0a = fmaf(uB[k], h0[k], gB0a);
            gB1a = fmaf(uB[k], h1[k], gB1a);
        }
    }
    float gA0 = gA0a + gA0b, gB0 = gB0a + gB0b;
    float gA1 = gA1a + gA1b, gB1 = gB1a + gB1b;

    // gA: sigmoid (i or f) via HW tanh
    float va0 = fmaf(0.5f, tanh_hw(0.5f * gA0), 0.5f);
    float va1 = fmaf(0.5f, tanh_hw(0.5f * gA1), 0.5f);
    // gB: g -> tanh (half0), o -> sigmoid (half1)
    float tb0 = tanh_hw(half ? 0.5f * gB0 : gB0);
    float tb1 = tanh_hw(half ? 0.5f * gB1 : gB1);
    float vb0 = half ? fmaf(0.5f, tb0, 0.5f) : tb0;
    float vb1 = half ? fmaf(0.5f, tb1, 0.5f) : tb1;

    float pa0 = __shfl_xor_sync(0xffffffffu, va0, 8);
    float pa1 = __shfl_xor_sync(0xffffffffu, va1, 8);
    float pb0 = __shfl_xor_sync(0xffffffffu, vb0, 8);
    float pb1 = __shfl_xor_sync(0xffffffffu, vb1, 8);

    c0 = fmaf(pa0, c0, va0 * vb0);
    c1 = fmaf(pa1, c1, va1 * vb1);
    float th0 = tanh_hw(c0);
    float th1 = tanh_hw(c1);
    hv0 = pb0 * th0;
    hv1 = pb1 * th1;

#pragma unroll
    for (int k = 0; k < HH; k++) {
        h0[k] = __shfl_sync(0xffffffffu, hv0, k, 16);
        h1[k] = __shfl_sync(0xffffffffu, hv1, k, 16);
    }
}

__global__ __launch_bounds__(32)
void lstm3_kernel(
    const float* __restrict__ x,
    const float* __restrict__ Wih1, const float* __restrict__ Whh1,
    const float* __restrict__ bih1, const float* __restrict__ bhh1,
    const float* __restrict__ Wih2, const float* __restrict__ Whh2,
    const float* __restrict__ bih2, const float* __restrict__ bhh2,
    const float* __restrict__ Wih3, const float* __restrict__ Whh3,
    const float* __restrict__ bih3, const float* __restrict__ bhh3,
    __half* __restrict__ out)
{
    const int tid  = threadIdx.x;
    const int grp  = tid >> 4;
    const int sub  = tid & 15;
    const int j    = sub & 7;
    const int half = sub >> 3;
    const int b0   = (blockIdx.x * 2 + grp) * 2;

    const int rowA = half * 8 + j;
    const int rowB = 16 + half * 8 + j;

    float wi1A[NIN], wi1B[NIN], uh1A[HH], uh1B[HH];
#pragma unroll
    for (int i = 0; i < NIN; i++) { wi1A[i] = Wih1[rowA * NIN + i]; wi1B[i] = Wih1[rowB * NIN + i]; }
#pragma unroll
    for (int k = 0; k < HH;  k++) { uh1A[k] = Whh1[rowA * HH + k]; uh1B[k] = Whh1[rowB * HH + k]; }
    float b1A = bih1[rowA] + bhh1[rowA];
    float b1B = bih1[rowB] + bhh1[rowB];

    float wi2A[HH], wi2B[HH], uh2A[HH], uh2B[HH];
#pragma unroll
    for (int k = 0; k < HH; k++) {
        wi2A[k] = Wih2[rowA * HH + k]; wi2B[k] = Wih2[rowB * HH + k];
        uh2A[k] = Whh2[rowA * HH + k]; uh2B[k] = Whh2[rowB * HH + k];
    }
    float b2A = bih2[rowA] + bhh2[rowA];
    float b2B = bih2[rowB] + bhh2[rowB];

    float wi3A[HH], wi3B[HH], uh3A[HH], uh3B[HH];
#pragma unroll
    for (int k = 0; k < HH; k++) {
        wi3A[k] = Wih3[rowA * HH + k]; wi3B[k] = Wih3[rowB * HH + k];
        uh3A[k] = Whh3[rowA * HH + k]; uh3B[k] = Whh3[rowB * HH + k];
    }
    float b3A = bih3[rowA] + bhh3[rowA];
    float b3B = bih3[rowB] + bhh3[rowB];

    float h1a[HH], h1b[HH], h2a[HH], h2b[HH], h3a[HH], h3b[HH];
#pragma unroll
    for (int k = 0; k < HH; k++) {
        h1a[k] = 0.f; h1b[k] = 0.f;
        h2a[k] = 0.f; h2b[k] = 0.f;
        h3a[k] = 0.f; h3b[k] = 0.f;
    }
    float c1a = 0.f, c1b = 0.f, c2a = 0.f, c2b = 0.f, c3a = 0.f, c3b = 0.f;

    const float* xr0 = x + (size_t)b0 * TT * NIN;
    const float* xr1 = xr0 + (size_t)TT * NIN;
    __half* op0 = out + (size_t)b0 * D_LSTM;
    __half* op1 = op0 + D_LSTM;

    float xn0[NIN], xn1[NIN];
#pragma unroll
    for (int i = 0; i < NIN; i++) { xn0[i] = xr0[i]; xn1[i] = xr1[i]; }

    float d0, d1, hv0, hv1;

    auto stepL1 = [&](const float (&xc0)[NIN], const float (&xc1)[NIN]) {
        cell_step2<NIN>(wi1A, wi1B, uh1A, uh1B, b1A, b1B, xc0, xc1,
                        h1a, h1b, c1a, c1b, half, d0, d1);
    };
    auto stepL2 = [&](const float (&i0)[HH], const float (&i1)[HH]) {
        cell_step2<HH>(wi2A, wi2B, uh2A, uh2B, b2A, b2B, i0, i1,
                       h2a, h2b, c2a, c2b, half, d0, d1);
    };
    auto stepL3 = [&](const float (&i0)[HH], const float (&i1)[HH]) {
        cell_step2<HH>(wi3A, wi3B, uh3A, uh3B, b3A, b3B, i0, i1,
                       h3a, h3b, c3a, c3b, half, hv0, hv1);
    };

    auto fetch_x = [&](int tn, float (&xc0)[NIN], float (&xc1)[NIN]) {
#pragma unroll
        for (int i = 0; i < NIN; i++) { xc0[i] = xn0[i]; xc1[i] = xn1[i]; }
#pragma unroll
        for (int i = 0; i < NIN; i++) {
            xn0[i] = xr0[tn * NIN + i];
            xn1[i] = xr1[tn * NIN + i];
        }
    };

    // ---- peeled prologue ----
    {   // i = 0: L1 only
        float xc0[NIN], xc1[NIN];
        fetch_x(1, xc0, xc1);
        stepL1(xc0, xc1);
    }
    {   // i = 1: L2 (t=0), L1 (t=1)
        float xc0[NIN], xc1[NIN];
        fetch_x(2, xc0, xc1);
        stepL2(h1a, h1b);
        stepL1(xc0, xc1);
    }

    // ---- main loop: i = 2 .. TT-1 ----
    for (int i = 2; i < TT; i++) {
        float xc0[NIN], xc1[NIN];
        const int tn = (i + 1 < TT) ? (i + 1) : (TT - 1);
        fetch_x(tn, xc0, xc1);

        stepL3(h2a, h2b);                 // t = i-2
        stepL2(h1a, h1b);                 // t = i-1
        stepL1(xc0, xc1);                 // t = i

        if (half == 0) {
            const int t = i - 2;
            op0[t * HH + j] = __float2half_rn(hv0);
            op1[t * HH + j] = __float2half_rn(hv1);
        }
    }

    // ---- peeled epilogue ----
    {
        stepL3(h2a, h2b);
        stepL2(h1a, h1b);
        if (half == 0) {
            const int t = TT - 2;
            op0[t * HH + j] = __float2half_rn(hv0);
            op1[t * HH + j] = __float2half_rn(hv1);
        }
    }
    {
        stepL3(h2a, h2b);
        if (half == 0) {
            const int t = TT - 1;
            op0[t * HH + j] = __float2half_rn(hv0);
            op1[t * HH + j] = __float2half_rn(hv1);
        }
    }
}

// ---------------------------------------------------------------------------
// fp16 tensor-core GEMM (fp32 accumulate): C = A[M,K] @ W[N,K]^T + bias.
// cp.async double-buffered, 2x2 warps, fragment double-buffering. (unchanged)
// ---------------------------------------------------------------------------

__device__ __forceinline__ void cp_async16(uint32_t dst, const void* src, int src_bytes) {
    asm volatile("cp.async.cg.shared.global [%0], [%1], 16, %2;\n"
                 :: "r"(dst), "l"(src), "r"(src_bytes));
}
__device__ __forceinline__ void cp_commit() {
    asm volatile("cp.async.commit_group;\n" ::: "memory");
}
template <int N>
__device__ __forceinline__ void cp_wait() {
    asm volatile("cp.async.wait_group %0;\n" :: "n"(N) : "memory");
}

__device__ __forceinline__ void mma_f16(float (&c)[4], const uint32_t (&a)[4],
                                        const uint32_t (&b)[2]) {
    asm volatile(
        "mma.sync.aligned.m16n8k16.row.col.f32.f16.f16.f32 "
        "{%0,%1,%2,%3}, {%4,%5,%6,%7}, {%8,%9}, {%0,%1,%2,%3};"
        : "+f"(c[0]), "+f"(c[1]), "+f"(c[2]), "+f"(c[3])
        : "r"(a[0]), "r"(a[1]), "r"(a[2]), "r"(a[3]), "r"(b[0]), "r"(b[1]));
}

template <int BM, int BN, bool RELU, bool OUT_HALF>
__global__ __launch_bounds__(128, 2)
void gemm_f16(const __half* __restrict__ A, const __half* __restrict__ W,
              const float* __restrict__ bias, void* __restrict__ Cv,
              int M, int N, int K)
{
    constexpr int BK = 64;
    constexpr int THREADS = 128;
    constexpr int WARPS_M = 2, WARPS_N = 2;
    constexpr int WM = BM / WARPS_M;
    constexpr int WN = BN / WARPS_N;
    constexpr int MT = WM / 16;
    constexpr int NT = WN / 8;
    constexpr int LDW = BK / 2 + 4;

    extern __shared__ uint32_t sm[];
    uint32_t* As = sm;
    uint32_t* Bs = sm + 2 * BM * LDW;

    const int tid  = threadIdx.x;
    const int lane = tid & 31;
    const int warp = tid >> 5;
    const int wm   = warp / WARPS_N;
    const int wn   = warp % WARPS_N;
    const int g    = lane >> 2;
    const int t    = lane & 3;

    const int m0 = blockIdx.y * BM;
    const int n0 = blockIdx.x * BN;

    const uint32_t as_smem = (uint32_t)__cvta_generic_to_shared(As);
    const uint32_t bs_smem = (uint32_t)__cvta_generic_to_shared(Bs);

    float acc[MT][NT][4];
#pragma unroll
    for (int i = 0; i < MT; i++)
#pragma unroll
        for (int j = 0; j < NT; j++)
#pragma unroll
            for (int q = 0; q < 4; q++) acc[i][j][q] = 0.f;

    constexpr int KQ = BK / 8;
    constexpr int A_ITERS = BM * KQ / THREADS;
    constexpr int B_ITERS = BN * KQ / THREADS;

    auto load_tiles = [&](int k0, int stage) {
        const uint32_t a_base = as_smem + (uint32_t)stage * BM * LDW * 4;
        const uint32_t b_base = bs_smem + (uint32_t)stage * BN * LDW * 4;
#pragma unroll
        for (int r = 0; r < A_ITERS; r++) {
            const int idx = tid + r * THREADS;
            const int row = idx / KQ;
            const int kq  = idx % KQ;
            const int kg  = k0 + kq * 8;
            const bool ok = kg < K;
            const __half* src = ok ? &A[(size_t)(m0 + row) * K + kg] : A;
            cp_async16(a_base + (row * LDW + kq * 4) * 4, src, ok ? 16 : 0);
        }
#pragma unroll
        for (int r = 0; r < B_ITERS; r++) {
            const int idx = tid + r * THREADS;
            const int row = idx / KQ;
            const int kq  = idx % KQ;
            const int kg  = k0 + kq * 8;
            const bool ok = (n0 + row) < N && kg < K;
            const __half* src = ok ? &W[(size_t)(n0 + row) * K + kg] : W;
            cp_async16(b_base + (row * LDW + kq * 4) * 4, src, ok ? 16 : 0);
        }
        cp_commit();
    };

    const int nk = (K + BK - 1) / BK;

    load_tiles(0, 0);

    uint32_t af[2][MT][4], bf[2][NT][2];

    for (int it = 0; it < nk; it++) {
        const int cur = it & 1;
        if (it + 1 < nk) {
            load_tiles((it + 1) * BK, (it + 1) & 1);
            cp_wait<1>();
        } else {
            cp_wait<0>();
        }
        __syncthreads();

        const uint32_t* Ac = As + cur * BM * LDW;
        const uint32_t* Bc = Bs + cur * BN * LDW;

        auto ldfrag = [&](int ks, int buf) {
            const int wb = ks * 8;
#pragma unroll
            for (int mt = 0; mt < MT; mt++) {
                const int r = wm * WM + mt * 16 + g;
                af[buf][mt][0] = Ac[(r    ) * LDW + wb + t    ];
                af[buf][mt][1] = Ac[(r + 8) * LDW + wb + t    ];
                af[buf][mt][2] = Ac[(r    ) * LDW + wb + t + 4];
                af[buf][mt][3] = Ac[(r + 8) * LDW + wb + t + 4];
            }
#pragma unroll
            for (int nt = 0; nt < NT; nt++) {
                const int cc = wn * WN + nt * 8 + g;
                bf[buf][nt][0] = Bc[cc * LDW + wb + t    ];
                bf[buf][nt][1] = Bc[cc * LDW + wb + t + 4];
            }
        };

        ldfrag(0, 0);
#pragma unroll
        for (int ks = 0; ks < 4; ks++) {
            const int cb = ks & 1;
            if (ks + 1 < 4)
                ldfrag(ks + 1, cb ^ 1);
#pragma unroll
            for (int mt = 0; mt < MT; mt++)
#pragma unroll
                for (int nt = 0; nt < NT; nt++)
                    mma_f16(acc[mt][nt], af[cb][mt], bf[cb][nt]);
        }
        __syncthreads();
    }

#pragma unroll
    for (int mt = 0; mt < MT; mt++) {
        const int r0 = m0 + wm * WM + mt * 16 + g;
        const int r1 = r0 + 8;
#pragma unroll
        for (int nt = 0; nt < NT; nt++) {
            const int cbase = n0 + wn * WN + nt * 8 + 2 * t;
            if (OUT_HALF) {
                const float bv0 = bias[cbase], bv1 = bias[cbase + 1];
                float v00 = acc[mt][nt][0] + bv0;
                float v01 = acc[mt][nt][1] + bv1;
                float v10 = acc[mt][nt][2] + bv0;
                float v11 = acc[mt][nt][3] + bv1;
                if (RELU) {
                    v00 = fmaxf(v00, 0.f); v01 = fmaxf(v01, 0.f);
                    v10 = fmaxf(v10, 0.f); v11 = fmaxf(v11, 0.f);
                }
                __half2* C = (__half2*)Cv;
                C[((size_t)r0 * N + cbase) >> 1] = __floats2half2_rn(v00, v01);
                C[((size_t)r1 * N + cbase) >> 1] = __floats2half2_rn(v10, v11);
            } else {
                float* C = (float*)Cv;
#pragma unroll
                for (int q = 0; q < 2; q++) {
                    const int cn = cbase + q;
                    if (cn < N) {
                        const float bv = bias[cn];
                        float v0 = acc[mt][nt][q] + bv;
                        float v1 = acc[mt][nt][2 + q] + bv;
                        if (RELU) { v0 = fmaxf(v0, 0.f); v1 = fmaxf(v1, 0.f); }
                        C[(size_t)r0 * N + cn] = v0;
                        C[(size_t)r1 * N + cn] = v1;
                    }
                }
            }
        }
    }
}

// ---------------------------------------------------------------------------
extern "C" void kernel_launch(void* const* d_in, const int* in_sizes, int n_in,
                              void* d_out, int out_size)
{
    const float* x    = (const float*)d_in[0];
    const float* Wih1 = (const float*)d_in[1];
    const float* Whh1 = (const float*)d_in[2];
    const float* bih1 = (const float*)d_in[3];
    const float* bhh1 = (const float*)d_in[4];
    const float* Wih2 = (const float*)d_in[5];
    const float* Whh2 = (const float*)d_in[6];
    const float* bih2 = (const float*)d_in[7];
    const float* bhh2 = (const float*)d_in[8];
    const float* Wih3 = (const float*)d_in[9];
    const float* Whh3 = (const float*)d_in[10];
    const float* bih3 = (const float*)d_in[11];
    const float* bhh3 = (const float*)d_in[12];
    const float* W1   = (const float*)d_in[13];
    const float* b1   = (const float*)d_in[14];
    const float* W2   = (const float*)d_in[15];
    const float* b2   = (const float*)d_in[16];
    const float* W3   = (const float*)d_in[17];
    const float* b3   = (const float*)d_in[18];
    float* out = (float*)d_out;

    __half *lstm_h, *a1h, *a2h, *w1h, *w2h, *w3h;
    cudaGetSymbolAddress((void**)&lstm_h, g_lstm_h);
    cudaGetSymbolAddress((void**)&a1h, g_a1h);
    cudaGetSymbolAddress((void**)&a2h, g_a2h);
    cudaGetSymbolAddress((void**)&w1h, g_w1h);
    cudaGetSymbolAddress((void**)&w2h, g_w2h);
    cudaGetSymbolAddress((void**)&w3h, g_w3h);

    constexpr int LDW = 36;
    constexpr int SMEM_128 = (2 * 128 * LDW + 2 * 128 * LDW) * 4;  // 73728
    constexpr int SMEM_64  = (2 * 128 * LDW + 2 * 64 * LDW) * 4;   // 55296

    static bool attr_done = false;
    if (!attr_done) {
        cudaFuncSetAttribute(gemm_f16<128, 128, true, true>,
                             cudaFuncAttributeMaxDynamicSharedMemorySize, SMEM_128);
        cudaFuncSetAttribute(gemm_f16<128, 64, true, true>,
                             cudaFuncAttributeMaxDynamicSharedMemorySize, SMEM_64);
        cudaFuncSetAttribute(gemm_f16<128, 64, false, false>,
                             cudaFuncAttributeMaxDynamicSharedMemorySize, SMEM_64);
        attr_done = true;
    }

    // 0) pre-convert weights to fp16
    {
        const int n4_1 = N1 * D_LSTM / 4;
        const int n4_2 = N2 * N1 / 4;
        const int n4_3 = N3 * N2 / 4;
        cvt_w_half<<<(n4_1 + 255) / 256, 256>>>((const float4*)W1, (__half2*)w1h, n4_1);
        cvt_w_half<<<(n4_2 + 255) / 256, 256>>>((const float4*)W2, (__half2*)w2h, n4_2);
        cvt_w_half<<<(n4_3 + 255) / 256, 256>>>((const float4*)W3, (__half2*)w3h, n4_3);
    }

    // 1) fused 3-layer LSTM (layer-skewed, HW tanh), 32-thr blocks, 512 blocks
    lstm3_kernel<<<BATCH / 4, 32>>>(x,
        Wih1, Whh1, bih1, bhh1,
        Wih2, Whh2, bih2, bhh2,
        Wih3, Whh3, bih3, bhh3,
        lstm_h);

    // 2) MLP head (fp16 mma, fp32 accumulate)
    {   // [2048,4872] x [4096,4872]^T -> relu -> [2048,4096] fp16
        dim3 grid(N1 / 128, BATCH / 128);
        gemm_f16<128, 128, true, true><<<grid, 128, SMEM_128>>>(
            lstm_h, w1h, b1, a1h, BATCH, N1, D_LSTM);
    }
    {   // [2048,4096] x [1024,4096]^T -> relu -> [2048,1024] fp16
        dim3 grid(N2 / 64, BATCH / 128);
        gemm_f16<128, 64, true, true><<<grid, 128, SMEM_64>>>(
            a1h, w2h, b2, a2h, BATCH, N2, N1);
    }
    {   // [2048,1024] x [609,1024]^T -> [2048,609] fp32
        dim3 grid((N3 + 63) / 64, BATCH / 128);
        gemm_f16<128, 64, false, false><<<grid, 128, SMEM_64>>>(
            a2h, w3h, b3, out, BATCH, N3, N2);
    }
}

// round 11
// speedup vs baseline: 1.2316x; 1.1201x over previous
#include <cuda_runtime.h>
#include <cuda_fp16.h>
#include <cstdint>

// Problem constants
#define BATCH 2048
#define TT    609
#define NIN   5
#define HH    8
#define D_LSTM (TT * HH)     // 4872
#define N1    4096
#define N2    1024
#define N3    609            // == TT

// Scratch (no cudaMalloc allowed) ---------------------------------------------
__device__ __half g_lstm_h[BATCH * D_LSTM];    // [2048, 4872] fp16
__device__ __half g_a1h[BATCH * N1];           // [2048, 4096] fp16
__device__ __half g_a2h[BATCH * N2];           // [2048, 1024] fp16
__device__ __half g_w1h[N1 * D_LSTM];          // fp16 W1
__device__ __half g_w2h[N2 * N1];              // fp16 W2
__device__ __half g_w3h[N3 * N2];              // fp16 W3

// ---------------------------------------------------------------------------
// weight fp32 -> fp16 conversion (once per launch)
// ---------------------------------------------------------------------------
__global__ void cvt_w_half(const float4* __restrict__ src, __half2* __restrict__ dst, int n4)
{
    int i = blockIdx.x * blockDim.x + threadIdx.x;
    if (i < n4) {
        float4 v = src[i];
        dst[2 * i + 0] = __floats2half2_rn(v.x, v.y);
        dst[2 * i + 1] = __floats2half2_rn(v.z, v.w);
    }
}

// ---------------------------------------------------------------------------
// Fused 3-layer LSTM: LAYER SKEW + HW tanh + ILP1 (1 elem / 16-lane group).
// 2 elements per warp -> 1024 warps (1.73 per SMSP): cross-warp latency hiding.
// Per-element math identical to R10 (bit-identical numerics).
// ---------------------------------------------------------------------------

__device__ __forceinline__ float tanh_hw(float x) {
    float y;
    asm("tanh.approx.f32 %0, %1;" : "=f"(y) : "f"(x));
    return y;
}

template <int NI>
__device__ __forceinline__ void cell_step1(
    const float (&wA)[NI], const float (&wB)[NI],
    const float (&uA)[HH], const float (&uB)[HH],
    float bA, float bB,
    const float (&in)[NI],
    float (&h)[HH], float& c, int half, float& hv)
{
    float gAa = bA, gAb = 0.f, gBa = bB, gBb = 0.f;
#pragma unroll
    for (int i = 0; i < NI; i++) {
        if (i & 1) {
            gAb = fmaf(wA[i], in[i], gAb);
            gBb = fmaf(wB[i], in[i], gBb);
        } else {
            gAa = fmaf(wA[i], in[i], gAa);
            gBa = fmaf(wB[i], in[i], gBa);
        }
    }
#pragma unroll
    for (int k = 0; k < HH; k++) {
        if (k & 1) {
            gAb = fmaf(uA[k], h[k], gAb);
            gBb = fmaf(uB[k], h[k], gBb);
        } else {
            gAa = fmaf(uA[k], h[k], gAa);
            gBa = fmaf(uB[k], h[k], gBa);
        }
    }
    float gA = gAa + gAb, gB = gBa + gBb;

    // gA: sigmoid (i or f) via HW tanh
    float va = fmaf(0.5f, tanh_hw(0.5f * gA), 0.5f);
    // gB: g -> tanh (half0), o -> sigmoid (half1)
    float tb = tanh_hw(half ? 0.5f * gB : gB);
    float vb = half ? fmaf(0.5f, tb, 0.5f) : tb;

    float pa = __shfl_xor_sync(0xffffffffu, va, 8);
    float pb = __shfl_xor_sync(0xffffffffu, vb, 8);

    c = fmaf(pa, c, va * vb);
    float th = tanh_hw(c);
    hv = pb * th;

#pragma unroll
    for (int k = 0; k < HH; k++)
        h[k] = __shfl_sync(0xffffffffu, hv, k, 16);
}

__global__ __launch_bounds__(32)
void lstm3_kernel(
    const float* __restrict__ x,
    const float* __restrict__ Wih1, const float* __restrict__ Whh1,
    const float* __restrict__ bih1, const float* __restrict__ bhh1,
    const float* __restrict__ Wih2, const float* __restrict__ Whh2,
    const float* __restrict__ bih2, const float* __restrict__ bhh2,
    const float* __restrict__ Wih3, const float* __restrict__ Whh3,
    const float* __restrict__ bih3, const float* __restrict__ bhh3,
    __half* __restrict__ out)
{
    const int tid  = threadIdx.x;
    const int grp  = tid >> 4;            // 0..1
    const int sub  = tid & 15;
    const int j    = sub & 7;
    const int half = sub >> 3;
    const int b    = blockIdx.x * 2 + grp;  // one element per 16-lane group

    const int rowA = half * 8 + j;
    const int rowB = 16 + half * 8 + j;

    float wi1A[NIN], wi1B[NIN], uh1A[HH], uh1B[HH];
#pragma unroll
    for (int i = 0; i < NIN; i++) { wi1A[i] = Wih1[rowA * NIN + i]; wi1B[i] = Wih1[rowB * NIN + i]; }
#pragma unroll
    for (int k = 0; k < HH;  k++) { uh1A[k] = Whh1[rowA * HH + k]; uh1B[k] = Whh1[rowB * HH + k]; }
    float b1A = bih1[rowA] + bhh1[rowA];
    float b1B = bih1[rowB] + bhh1[rowB];

    float wi2A[HH], wi2B[HH], uh2A[HH], uh2B[HH];
#pragma unroll
    for (int k = 0; k < HH; k++) {
        wi2A[k] = Wih2[rowA * HH + k]; wi2B[k] = Wih2[rowB * HH + k];
        uh2A[k] = Whh2[rowA * HH + k]; uh2B[k] = Whh2[rowB * HH + k];
    }
    float b2A = bih2[rowA] + bhh2[rowA];
    float b2B = bih2[rowB] + bhh2[rowB];

    float wi3A[HH], wi3B[HH], uh3A[HH], uh3B[HH];
#pragma unroll
    for (int k = 0; k < HH; k++) {
        wi3A[k] = Wih3[rowA * HH + k]; wi3B[k] = Wih3[rowB * HH + k];
        uh3A[k] = Whh3[rowA * HH + k]; uh3B[k] = Whh3[rowB * HH + k];
    }
    float b3A = bih3[rowA] + bhh3[rowA];
    float b3B = bih3[rowB] + bhh3[rowB];

    float h1[HH], h2[HH], h3[HH];
#pragma unroll
    for (int k = 0; k < HH; k++) { h1[k] = 0.f; h2[k] = 0.f; h3[k] = 0.f; }
    float c1 = 0.f, c2 = 0.f, c3 = 0.f;

    const float* xr = x + (size_t)b * TT * NIN;
    __half* op = out + (size_t)b * D_LSTM;

    float xn[NIN];
#pragma unroll
    for (int i = 0; i < NIN; i++) xn[i] = xr[i];

    float d, hv;

    auto stepL1 = [&](const float (&xc)[NIN]) {
        cell_step1<NIN>(wi1A, wi1B, uh1A, uh1B, b1A, b1B, xc, h1, c1, half, d);
    };
    auto stepL2 = [&](const float (&i0)[HH]) {
        cell_step1<HH>(wi2A, wi2B, uh2A, uh2B, b2A, b2B, i0, h2, c2, half, d);
    };
    auto stepL3 = [&](const float (&i0)[HH]) {
        cell_step1<HH>(wi3A, wi3B, uh3A, uh3B, b3A, b3B, i0, h3, c3, half, hv);
    };

    auto fetch_x = [&](int tn, float (&xc)[NIN]) {
#pragma unroll
        for (int i = 0; i < NIN; i++) xc[i] = xn[i];
#pragma unroll
        for (int i = 0; i < NIN; i++) xn[i] = xr[tn * NIN + i];
    };

    // ---- peeled prologue ----
    {   // i = 0: L1 only
        float xc[NIN];
        fetch_x(1, xc);
        stepL1(xc);
    }
    {   // i = 1: L2 (t=0), L1 (t=1)
        float xc[NIN];
        fetch_x(2, xc);
        stepL2(h1);
        stepL1(xc);
    }

    // ---- main loop: i = 2 .. TT-1 ----
    for (int i = 2; i < TT; i++) {
        float xc[NIN];
        const int tn = (i + 1 < TT) ? (i + 1) : (TT - 1);
        fetch_x(tn, xc);

        stepL3(h2);                       // t = i-2 (reads h2 pre-update)
        stepL2(h1);                       // t = i-1 (reads h1 pre-update)
        stepL1(xc);                       // t = i

        if (half == 0)
            op[(i - 2) * HH + j] = __float2half_rn(hv);
    }

    // ---- peeled epilogue ----
    {
        stepL3(h2);
        stepL2(h1);
        if (half == 0)
            op[(TT - 2) * HH + j] = __float2half_rn(hv);
    }
    {
        stepL3(h2);
        if (half == 0)
            op[(TT - 1) * HH + j] = __float2half_rn(hv);
    }
}

// ---------------------------------------------------------------------------
// fp16 tensor-core GEMM (fp32 accumulate): C = A[M,K] @ W[N,K]^T + bias.
// cp.async double-buffered, 2x2 warps, fragment double-buffering. (unchanged)
// ---------------------------------------------------------------------------

__device__ __forceinline__ void cp_async16(uint32_t dst, const void* src, int src_bytes) {
    asm volatile("cp.async.cg.shared.global [%0], [%1], 16, %2;\n"
                 :: "r"(dst), "l"(src), "r"(src_bytes));
}
__device__ __forceinline__ void cp_commit() {
    asm volatile("cp.async.commit_group;\n" ::: "memory");
}
template <int N>
__device__ __forceinline__ void cp_wait() {
    asm volatile("cp.async.wait_group %0;\n" :: "n"(N) : "memory");
}

__device__ __forceinline__ void mma_f16(float (&c)[4], const uint32_t (&a)[4],
                                        const uint32_t (&b)[2]) {
    asm volatile(
        "mma.sync.aligned.m16n8k16.row.col.f32.f16.f16.f32 "
        "{%0,%1,%2,%3}, {%4,%5,%6,%7}, {%8,%9}, {%0,%1,%2,%3};"
        : "+f"(c[0]), "+f"(c[1]), "+f"(c[2]), "+f"(c[3])
        : "r"(a[0]), "r"(a[1]), "r"(a[2]), "r"(a[3]), "r"(b[0]), "r"(b[1]));
}

template <int BM, int BN, bool RELU, bool OUT_HALF>
__global__ __launch_bounds__(128, 2)
void gemm_f16(const __half* __restrict__ A, const __half* __restrict__ W,
              const float* __restrict__ bias, void* __restrict__ Cv,
              int M, int N, int K)
{
    constexpr int BK = 64;
    constexpr int THREADS = 128;
    constexpr int WARPS_M = 2, WARPS_N = 2;
    constexpr int WM = BM / WARPS_M;
    constexpr int WN = BN / WARPS_N;
    constexpr int MT = WM / 16;
    constexpr int NT = WN / 8;
    constexpr int LDW = BK / 2 + 4;

    extern __shared__ uint32_t sm[];
    uint32_t* As = sm;
    uint32_t* Bs = sm + 2 * BM * LDW;

    const int tid  = threadIdx.x;
    const int lane = tid & 31;
    const int warp = tid >> 5;
    const int wm   = warp / WARPS_N;
    const int wn   = warp % WARPS_N;
    const int g    = lane >> 2;
    const int t    = lane & 3;

    const int m0 = blockIdx.y * BM;
    const int n0 = blockIdx.x * BN;

    const uint32_t as_smem = (uint32_t)__cvta_generic_to_shared(As);
    const uint32_t bs_smem = (uint32_t)__cvta_generic_to_shared(Bs);

    float acc[MT][NT][4];
#pragma unroll
    for (int i = 0; i < MT; i++)
#pragma unroll
        for (int j = 0; j < NT; j++)
#pragma unroll
            for (int q = 0; q < 4; q++) acc[i][j][q] = 0.f;

    constexpr int KQ = BK / 8;
    constexpr int A_ITERS = BM * KQ / THREADS;
    constexpr int B_ITERS = BN * KQ / THREADS;

    auto load_tiles = [&](int k0, int stage) {
        const uint32_t a_base = as_smem + (uint32_t)stage * BM * LDW * 4;
        const uint32_t b_base = bs_smem + (uint32_t)stage * BN * LDW * 4;
#pragma unroll
        for (int r = 0; r < A_ITERS; r++) {
            const int idx = tid + r * THREADS;
            const int row = idx / KQ;
            const int kq  = idx % KQ;
            const int kg  = k0 + kq * 8;
            const bool ok = kg < K;
            const __half* src = ok ? &A[(size_t)(m0 + row) * K + kg] : A;
            cp_async16(a_base + (row * LDW + kq * 4) * 4, src, ok ? 16 : 0);
        }
#pragma unroll
        for (int r = 0; r < B_ITERS; r++) {
            const int idx = tid + r * THREADS;
            const int row = idx / KQ;
            const int kq  = idx % KQ;
            const int kg  = k0 + kq * 8;
            const bool ok = (n0 + row) < N && kg < K;
            const __half* src = ok ? &W[(size_t)(n0 + row) * K + kg] : W;
            cp_async16(b_base + (row * LDW + kq * 4) * 4, src, ok ? 16 : 0);
        }
        cp_commit();
    };

    const int nk = (K + BK - 1) / BK;

    load_tiles(0, 0);

    uint32_t af[2][MT][4], bf[2][NT][2];

    for (int it = 0; it < nk; it++) {
        const int cur = it & 1;
        if (it + 1 < nk) {
            load_tiles((it + 1) * BK, (it + 1) & 1);
            cp_wait<1>();
        } else {
            cp_wait<0>();
        }
        __syncthreads();

        const uint32_t* Ac = As + cur * BM * LDW;
        const uint32_t* Bc = Bs + cur * BN * LDW;

        auto ldfrag = [&](int ks, int buf) {
            const int wb = ks * 8;
#pragma unroll
            for (int mt = 0; mt < MT; mt++) {
                const int r = wm * WM + mt * 16 + g;
                af[buf][mt][0] = Ac[(r    ) * LDW + wb + t    ];
                af[buf][mt][1] = Ac[(r + 8) * LDW + wb + t    ];
                af[buf][mt][2] = Ac[(r    ) * LDW + wb + t + 4];
                af[buf][mt][3] = Ac[(r + 8) * LDW + wb + t + 4];
            }
#pragma unroll
            for (int nt = 0; nt < NT; nt++) {
                const int cc = wn * WN + nt * 8 + g;
                bf[buf][nt][0] = Bc[cc * LDW + wb + t    ];
                bf[buf][nt][1] = Bc[cc * LDW + wb + t + 4];
            }
        };

        ldfrag(0, 0);
#pragma unroll
        for (int ks = 0; ks < 4; ks++) {
            const int cb = ks & 1;
            if (ks + 1 < 4)
                ldfrag(ks + 1, cb ^ 1);
#pragma unroll
            for (int mt = 0; mt < MT; mt++)
#pragma unroll
                for (int nt = 0; nt < NT; nt++)
                    mma_f16(acc[mt][nt], af[cb][mt], bf[cb][nt]);
        }
        __syncthreads();
    }

#pragma unroll
    for (int mt = 0; mt < MT; mt++) {
        const int r0 = m0 + wm * WM + mt * 16 + g;
        const int r1 = r0 + 8;
#pragma unroll
        for (int nt = 0; nt < NT; nt++) {
            const int cbase = n0 + wn * WN + nt * 8 + 2 * t;
            if (OUT_HALF) {
                const float bv0 = bias[cbase], bv1 = bias[cbase + 1];
                float v00 = acc[mt][nt][0] + bv0;
                float v01 = acc[mt][nt][1] + bv1;
                float v10 = acc[mt][nt][2] + bv0;
                float v11 = acc[mt][nt][3] + bv1;
                if (RELU) {
                    v00 = fmaxf(v00, 0.f); v01 = fmaxf(v01, 0.f);
                    v10 = fmaxf(v10, 0.f); v11 = fmaxf(v11, 0.f);
                }
                __half2* C = (__half2*)Cv;
                C[((size_t)r0 * N + cbase) >> 1] = __floats2half2_rn(v00, v01);
                C[((size_t)r1 * N + cbase) >> 1] = __floats2half2_rn(v10, v11);
            } else {
                float* C = (float*)Cv;
#pragma unroll
                for (int q = 0; q < 2; q++) {
                    const int cn = cbase + q;
                    if (cn < N) {
                        const float bv = bias[cn];
                        float v0 = acc[mt][nt][q] + bv;
                        float v1 = acc[mt][nt][2 + q] + bv;
                        if (RELU) { v0 = fmaxf(v0, 0.f); v1 = fmaxf(v1, 0.f); }
                        C[(size_t)r0 * N + cn] = v0;
                        C[(size_t)r1 * N + cn] = v1;
                    }
                }
            }
        }
    }
}

// ---------------------------------------------------------------------------
extern "C" void kernel_launch(void* const* d_in, const int* in_sizes, int n_in,
                              void* d_out, int out_size)
{
    const float* x    = (const float*)d_in[0];
    const float* Wih1 = (const float*)d_in[1];
    const float* Whh1 = (const float*)d_in[2];
    const float* bih1 = (const float*)d_in[3];
    const float* bhh1 = (const float*)d_in[4];
    const float* Wih2 = (const float*)d_in[5];
    const float* Whh2 = (const float*)d_in[6];
    const float* bih2 = (const float*)d_in[7];
    const float* bhh2 = (const float*)d_in[8];
    const float* Wih3 = (const float*)d_in[9];
    const float* Whh3 = (const float*)d_in[10];
    const float* bih3 = (const float*)d_in[11];
    const float* bhh3 = (const float*)d_in[12];
    const float* W1   = (const float*)d_in[13];
    const float* b1   = (const float*)d_in[14];
    const float* W2   = (const float*)d_in[15];
    const float* b2   = (const float*)d_in[16];
    const float* W3   = (const float*)d_in[17];
    const float* b3   = (const float*)d_in[18];
    float* out = (float*)d_out;

    __half *lstm_h, *a1h, *a2h, *w1h, *w2h, *w3h;
    cudaGetSymbolAddress((void**)&lstm_h, g_lstm_h);
    cudaGetSymbolAddress((void**)&a1h, g_a1h);
    cudaGetSymbolAddress((void**)&a2h, g_a2h);
    cudaGetSymbolAddress((void**)&w1h, g_w1h);
    cudaGetSymbolAddress((void**)&w2h, g_w2h);
    cudaGetSymbolAddress((void**)&w3h, g_w3h);

    constexpr int LDW = 36;
    constexpr int SMEM_128 = (2 * 128 * LDW + 2 * 128 * LDW) * 4;  // 73728
    constexpr int SMEM_64  = (2 * 128 * LDW + 2 * 64 * LDW) * 4;   // 55296

    static bool attr_done = false;
    if (!attr_done) {
        cudaFuncSetAttribute(gemm_f16<128, 128, true, true>,
                             cudaFuncAttributeMaxDynamicSharedMemorySize, SMEM_128);
        cudaFuncSetAttribute(gemm_f16<128, 64, true, true>,
                             cudaFuncAttributeMaxDynamicSharedMemorySize, SMEM_64);
        cudaFuncSetAttribute(gemm_f16<128, 64, false, false>,
                             cudaFuncAttributeMaxDynamicSharedMemorySize, SMEM_64);
        attr_done = true;
    }

    // 0) pre-convert weights to fp16
    {
        const int n4_1 = N1 * D_LSTM / 4;
        const int n4_2 = N2 * N1 / 4;
        const int n4_3 = N3 * N2 / 4;
        cvt_w_half<<<(n4_1 + 255) / 256, 256>>>((const float4*)W1, (__half2*)w1h, n4_1);
        cvt_w_half<<<(n4_2 + 255) / 256, 256>>>((const float4*)W2, (__half2*)w2h, n4_2);
        cvt_w_half<<<(n4_3 + 255) / 256, 256>>>((const float4*)W3, (__half2*)w3h, n4_3);
    }

    // 1) fused 3-layer LSTM (skewed, HW tanh, ILP1): 1024 blocks x 32 threads
    lstm3_kernel<<<BATCH / 2, 32>>>(x,
        Wih1, Whh1, bih1, bhh1,
        Wih2, Whh2, bih2, bhh2,
        Wih3, Whh3, bih3, bhh3,
        lstm_h);

    // 2) MLP head (fp16 mma, fp32 accumulate)
    {   // [2048,4872] x [4096,4872]^T -> relu -> [2048,4096] fp16
        dim3 grid(N1 / 128, BATCH / 128);
        gemm_f16<128, 128, true, true><<<grid, 128, SMEM_128>>>(
            lstm_h, w1h, b1, a1h, BATCH, N1, D_LSTM);
    }
    {   // [2048,4096] x [1024,4096]^T -> relu -> [2048,1024] fp16
        dim3 grid(N2 / 64, BATCH / 128);
        gemm_f16<128, 64, true, true><<<grid, 128, SMEM_64>>>(
            a1h, w2h, b2, a2h, BATCH, N2, N1);
    }
    {   // [2048,1024] x [609,1024]^T -> [2048,609] fp32
        dim3 grid((N3 + 63) / 64, BATCH / 128);
        gemm_f16<128, 64, false, false><<<grid, 128, SMEM_64>>>(
            a2h, w3h, b3, out, BATCH, N3, N2);
    }
}